// round 2
// baseline (speedup 1.0000x reference)
#include <cuda_runtime.h>

// LNSLinear == plain fp32 GEMM: y = x @ W^T + bias.
// The reference's log-domain max/rescale is an exact algebraic identity for
// the dot product; only rounding differs (~1e-6 rel), far under the 1e-3 gate.
//
// Shapes fixed by the dataset: x[512,512], weight[512,512], bias[512].
// Plan: split-K=4 SIMT fp32 GEMM (deterministic partials into __device__
// scratch, no atomics), then a reduce+bias kernel.

namespace {
constexpr int M = 512;   // batch rows of x
constexpr int N = 512;   // out features (rows of weight)
constexpr int K = 512;
constexpr int SPLITK = 4;
constexpr int KC = K / SPLITK;   // 128 per CTA
constexpr int BM = 64, BN = 64, BK = 32;
}

// 4 MB deterministic scratch for split-K partials (alloc-free per harness rules).
__device__ float g_partial[SPLITK * M * N];

__global__ __launch_bounds__(256, 2) void lns_gemm_partial(
    const float* __restrict__ x, const float* __restrict__ w) {
    __shared__ float As[BK][BM];   // [k][m] transposed for conflict-free compute reads
    __shared__ float Bs[BK][BN];   // [k][n]

    const int m0 = blockIdx.y * BM;
    const int n0 = blockIdx.x * BN;
    const int kz = blockIdx.z;

    const int t  = threadIdx.x;          // 0..255
    const int tx = t & 15;               // n micro-tile index (16)
    const int ty = t >> 4;               // m micro-tile index (16)

    // Loader mapping: lrow = t % 64 keeps STS into As[k][m] conflict-free
    // (bank = m % 32, distinct per warp).
    const int lrow = t & 63;
    const int lc4  = t >> 6;             // 0..3 (float4 column group)

    const float* xA = x + (size_t)(m0 + lrow) * K + kz * KC;
    const float* wB = w + (size_t)(n0 + lrow) * K + kz * KC;

    float acc[4][4];
#pragma unroll
    for (int i = 0; i < 4; i++)
#pragma unroll
        for (int j = 0; j < 4; j++) acc[i][j] = 0.0f;

    for (int kc = 0; kc < KC; kc += BK) {
        // Global -> shared (transposed store). 2 float4 per tile per thread.
#pragma unroll
        for (int h = 0; h < 2; h++) {
            const int c4 = lc4 + 4 * h;          // 0..7
            const float4 va = *reinterpret_cast<const float4*>(xA + kc + c4 * 4);
            const float4 vb = *reinterpret_cast<const float4*>(wB + kc + c4 * 4);
            As[c4 * 4 + 0][lrow] = va.x;
            As[c4 * 4 + 1][lrow] = va.y;
            As[c4 * 4 + 2][lrow] = va.z;
            As[c4 * 4 + 3][lrow] = va.w;
            Bs[c4 * 4 + 0][lrow] = vb.x;
            Bs[c4 * 4 + 1][lrow] = vb.y;
            Bs[c4 * 4 + 2][lrow] = vb.z;
            Bs[c4 * 4 + 3][lrow] = vb.w;
        }
        __syncthreads();

#pragma unroll
        for (int k = 0; k < BK; k++) {
            const float4 a = *reinterpret_cast<const float4*>(&As[k][ty * 4]);
            const float4 b = *reinterpret_cast<const float4*>(&Bs[k][tx * 4]);
            const float av[4] = {a.x, a.y, a.z, a.w};
            const float bv[4] = {b.x, b.y, b.z, b.w};
#pragma unroll
            for (int i = 0; i < 4; i++)
#pragma unroll
                for (int j = 0; j < 4; j++) acc[i][j] += av[i] * bv[j];
        }
        __syncthreads();
    }

    // Deterministic partial store (coalesced float4 rows).
    float* dst = g_partial + ((size_t)kz * M + (m0 + ty * 4)) * N + n0 + tx * 4;
#pragma unroll
    for (int i = 0; i < 4; i++) {
        float4 v;
        v.x = acc[i][0]; v.y = acc[i][1]; v.z = acc[i][2]; v.w = acc[i][3];
        *reinterpret_cast<float4*>(dst + (size_t)i * N) = v;
    }
}

__global__ __launch_bounds__(256) void lns_reduce_bias(
    const float* __restrict__ bias, float* __restrict__ out) {
    const int idx = blockIdx.x * 256 + threadIdx.x;    // float4 index over M*N/4
    const int n = (idx * 4) & (N - 1);                 // column (multiple of 4)
    const float4* p = reinterpret_cast<const float4*>(g_partial);
    constexpr int Q = M * N / 4;
    const float4 s0 = p[idx];
    const float4 s1 = p[idx + Q];
    const float4 s2 = p[idx + 2 * Q];
    const float4 s3 = p[idx + 3 * Q];
    const float4 bb = *reinterpret_cast<const float4*>(bias + n);
    float4 r;
    r.x = s0.x + s1.x + s2.x + s3.x + bb.x;
    r.y = s0.y + s1.y + s2.y + s3.y + bb.y;
    r.z = s0.z + s1.z + s2.z + s3.z + bb.z;
    r.w = s0.w + s1.w + s2.w + s3.w + bb.w;
    reinterpret_cast<float4*>(out)[idx] = r;
}

extern "C" void kernel_launch(void* const* d_in, const int* in_sizes, int n_in,
                              void* d_out, int out_size) {
    (void)in_sizes; (void)n_in; (void)out_size;
    const float* x    = (const float*)d_in[0];   // [512, 512]
    const float* w    = (const float*)d_in[1];   // [512, 512]
    const float* bias = (const float*)d_in[2];   // [512]
    float* out = (float*)d_out;                  // [512, 512] fp32

    dim3 grid(N / BN, M / BM, SPLITK);           // 8 x 8 x 4 = 256 CTAs
    lns_gemm_partial<<<grid, 256>>>(x, w);
    lns_reduce_bias<<<(M * N / 4) / 256, 256>>>(bias, out);
}

// round 4
// speedup vs baseline: 2.7143x; 2.7143x over previous
#include <cuda_runtime.h>
#include <cuda_bf16.h>
#include <cstdint>

// LNSLinear == y = x @ W^T + bias (log-domain max/rescale is an exact identity).
// R3: tcgen05 is rejected by this harness's ptxas target (sm_103, no 'a'), so
// use the legacy register-resident tensor path: mma.sync.m16n8k16 bf16 (HMMA).
// fp32 precision via 2-way bf16 split, 3 products: hi*hi + lo*hi + hi*lo.
//
// Kernel 1: convert x,w fp32 -> bf16 hi/lo planes (device scratch, 2MB).
// Kernel 2: GEMM, 128 CTAs of 64(M)x32(N), 4 warps, cp.async double-buffered
//           SMEM (KC=64, 128B swizzled rows, conflict-free ldmatrix).

namespace {
constexpr int Mdim = 512, Ndim = 512, Kdim = 512;
constexpr int TM = 64, TN = 32, KC = 64;
constexpr int NCHUNK = Kdim / KC;          // 8
// SMEM stage layout (bytes): Ah | Al | Bh | Bl, 128B rows (KC bf16)
constexpr int OFF_AH = 0;
constexpr int OFF_AL = TM * 128;           // 8192
constexpr int OFF_BH = 2 * TM * 128;       // 16384
constexpr int OFF_BL = 2 * TM * 128 + TN * 128;  // 20480
constexpr int STAGE  = 2 * TM * 128 + 2 * TN * 128;  // 24576
constexpr int SMEM_TOTAL = 2 * STAGE;      // 49152
}

// bf16 planes: [0]=x_hi, [1]=x_lo, [2]=w_hi, [3]=w_lo
__device__ __nv_bfloat16 g_planes[4][Mdim * Kdim];

__device__ __forceinline__ uint32_t smem_u32(const void* p) {
    uint32_t a;
    asm("{ .reg .u64 t; cvta.to.shared.u64 t, %1; cvt.u32.u64 %0, t; }"
        : "=r"(a) : "l"(p));
    return a;
}

__device__ __forceinline__ void cp16(uint32_t dst, const void* src) {
    asm volatile("cp.async.cg.shared.global [%0], [%1], 16;"
                 :: "r"(dst), "l"(src));
}

__device__ __forceinline__ void ldm_x4(uint32_t* r, uint32_t addr) {
    asm volatile(
        "ldmatrix.sync.aligned.m8n8.x4.shared.b16 {%0, %1, %2, %3}, [%4];"
        : "=r"(r[0]), "=r"(r[1]), "=r"(r[2]), "=r"(r[3]) : "r"(addr));
}

__device__ __forceinline__ void mma16816(float* d, const uint32_t* a,
                                         const uint32_t* b) {
    asm volatile(
        "mma.sync.aligned.m16n8k16.row.col.f32.bf16.bf16.f32 "
        "{%0, %1, %2, %3}, {%4, %5, %6, %7}, {%8, %9}, {%0, %1, %2, %3};"
        : "+f"(d[0]), "+f"(d[1]), "+f"(d[2]), "+f"(d[3])
        : "r"(a[0]), "r"(a[1]), "r"(a[2]), "r"(a[3]), "r"(b[0]), "r"(b[1]));
}

// ---------------- Kernel 1: fp32 -> bf16 hi/lo planes ----------------
__global__ __launch_bounds__(256) void convert_hilo(
    const float* __restrict__ x, const float* __restrict__ w) {
    const int idx = blockIdx.x * 256 + threadIdx.x;   // float4 id, 131072 total
    const bool isx = idx < 65536;
    const int local = idx & 65535;
    const float4 v = reinterpret_cast<const float4*>(isx ? x : w)[local];
    __nv_bfloat162 h01 = __float22bfloat162_rn(make_float2(v.x, v.y));
    __nv_bfloat162 h23 = __float22bfloat162_rn(make_float2(v.z, v.w));
    const float2 f01 = __bfloat1622float2(h01);
    const float2 f23 = __bfloat1622float2(h23);
    __nv_bfloat162 l01 = __float22bfloat162_rn(make_float2(v.x - f01.x, v.y - f01.y));
    __nv_bfloat162 l23 = __float22bfloat162_rn(make_float2(v.z - f23.x, v.w - f23.y));
    const int p = isx ? 0 : 2;
    reinterpret_cast<uint2*>(g_planes[p])[local] =
        make_uint2(*reinterpret_cast<uint32_t*>(&h01),
                   *reinterpret_cast<uint32_t*>(&h23));
    reinterpret_cast<uint2*>(g_planes[p + 1])[local] =
        make_uint2(*reinterpret_cast<uint32_t*>(&l01),
                   *reinterpret_cast<uint32_t*>(&l23));
}

// ---------------- Kernel 2: split-bf16 GEMM via mma.sync ----------------
__global__ __launch_bounds__(128, 2) void lns_hmma_gemm(
    const float* __restrict__ bias, float* __restrict__ out) {
    extern __shared__ char smem[];
    const uint32_t sb = smem_u32(smem);
    const int t = threadIdx.x;
    const int wid = t >> 5;
    const int l = t & 31;
    const int m0 = blockIdx.y * TM;
    const int n0 = blockIdx.x * TN;

    // ---- cp.async loader mapping (per chunk) ----
    // A planes: 512 x 16B per plane; B planes: 256 x 16B per plane.
    const int ar = t >> 3;            // used with +128-row strides below
    const int ac16 = t & 7;           // 16B column group 0..7

    auto load_chunk = [&](int c, int buf) {
        const int kb = c * KC;
        const uint32_t s = sb + (uint32_t)buf * STAGE;
#pragma unroll
        for (int i = 0; i < 4; ++i) {
            const int r = ar + i * 16;            // 0..63
            const uint32_t byte = (uint32_t)(r * 128 + ((ac16 * 16) ^ ((r & 7) * 16)));
            const size_t src = (size_t)(m0 + r) * Kdim + kb + ac16 * 8;
            cp16(s + OFF_AH + byte, &g_planes[0][src]);
            cp16(s + OFF_AL + byte, &g_planes[1][src]);
        }
#pragma unroll
        for (int i = 0; i < 2; ++i) {
            const int r = ar + i * 16;            // 0..31
            const uint32_t byte = (uint32_t)(r * 128 + ((ac16 * 16) ^ ((r & 7) * 16)));
            const size_t src = (size_t)(n0 + r) * Kdim + kb + ac16 * 8;
            cp16(s + OFF_BH + byte, &g_planes[2][src]);
            cp16(s + OFF_BL + byte, &g_planes[3][src]);
        }
        asm volatile("cp.async.commit_group;" ::: "memory");
    };

    // ---- ldmatrix per-lane address precompute ----
    // A fragment (16x16): lanes 0-15 -> rows l, k+0; lanes 16-31 -> rows l-16, k+8.
    const int a_row = wid * 16 + (l & 15);
    const uint32_t a_xr = (uint32_t)((a_row & 7) * 16);
    const uint32_t a_rb = (uint32_t)(a_row * 128);
    const uint32_t a_c0 = (uint32_t)((l >> 4) * 16);      // bytes (8 bf16)
    // B fragments: lanes 0-7: n0-7@k0; 8-15: n0-7@k8; 16-23: n8-15@k0; 24-31: n8-15@k8
    const int b_row = (l & 7) + ((l >> 4) << 3);
    const uint32_t b_xr  = (uint32_t)((b_row & 7) * 16);
    const uint32_t b_rb0 = (uint32_t)(b_row * 128);
    const uint32_t b_rb1 = (uint32_t)((b_row + 16) * 128);
    const uint32_t b_xr1 = b_xr;                          // (row+16)&7 == row&7
    const uint32_t b_c0 = (uint32_t)(((l >> 3) & 1) * 16);

    float d[4][4];
#pragma unroll
    for (int i = 0; i < 4; ++i)
#pragma unroll
        for (int j = 0; j < 4; ++j) d[i][j] = 0.0f;

    load_chunk(0, 0);

    for (int c = 0; c < NCHUNK; ++c) {
        if (c < NCHUNK - 1) {
            load_chunk(c + 1, (c + 1) & 1);
            asm volatile("cp.async.wait_group 1;" ::: "memory");
        } else {
            asm volatile("cp.async.wait_group 0;" ::: "memory");
        }
        __syncthreads();

        const uint32_t s = sb + (uint32_t)(c & 1) * STAGE;
        const uint32_t ah_b = s + OFF_AH + a_rb;
        const uint32_t al_b = s + OFF_AL + a_rb;
        const uint32_t bh0 = s + OFF_BH + b_rb0;
        const uint32_t bh1 = s + OFF_BH + b_rb1;
        const uint32_t bl0 = s + OFF_BL + b_rb0;
        const uint32_t bl1 = s + OFF_BL + b_rb1;

#pragma unroll
        for (int ks = 0; ks < 4; ++ks) {
            const uint32_t cA = (uint32_t)(ks * 32) + a_c0;
            const uint32_t cB = (uint32_t)(ks * 32) + b_c0;
            uint32_t ah[4], al[4], bh[8], bl[8];
            ldm_x4(ah, ah_b + (cA ^ a_xr));
            ldm_x4(al, al_b + (cA ^ a_xr));
            ldm_x4(bh,     bh0 + (cB ^ b_xr));
            ldm_x4(bh + 4, bh1 + (cB ^ b_xr1));
            ldm_x4(bl,     bl0 + (cB ^ b_xr));
            ldm_x4(bl + 4, bl1 + (cB ^ b_xr1));
#pragma unroll
            for (int nt = 0; nt < 4; ++nt) {
                mma16816(d[nt], ah, bh + 2 * nt);   // hi*hi
                mma16816(d[nt], al, bh + 2 * nt);   // lo*hi
                mma16816(d[nt], ah, bl + 2 * nt);   // hi*lo
            }
        }
        __syncthreads();
    }

    // ---- Epilogue: D frag lane l: rows g,g+8 (g=l>>2), col pair (l&3)*2 ----
    const int g = l >> 2;
    const int tc = l & 3;
    const int row0 = m0 + wid * 16 + g;
#pragma unroll
    for (int nt = 0; nt < 4; ++nt) {
        const int col = n0 + nt * 8 + tc * 2;
        const float2 bv = *reinterpret_cast<const float2*>(bias + col);
        float2 o0, o1;
        o0.x = d[nt][0] + bv.x;  o0.y = d[nt][1] + bv.y;
        o1.x = d[nt][2] + bv.x;  o1.y = d[nt][3] + bv.y;
        *reinterpret_cast<float2*>(out + (size_t)row0 * Ndim + col) = o0;
        *reinterpret_cast<float2*>(out + (size_t)(row0 + 8) * Ndim + col) = o1;
    }
}

extern "C" void kernel_launch(void* const* d_in, const int* in_sizes, int n_in,
                              void* d_out, int out_size) {
    (void)in_sizes; (void)n_in; (void)out_size;
    const float* x    = (const float*)d_in[0];   // [512, 512]
    const float* w    = (const float*)d_in[1];   // [512, 512]
    const float* bias = (const float*)d_in[2];   // [512]
    float* out = (float*)d_out;                  // [512, 512] fp32

    convert_hilo<<<512, 256>>>(x, w);

    static bool attr_set = false;
    if (!attr_set) {
        cudaFuncSetAttribute(lns_hmma_gemm,
                             cudaFuncAttributeMaxDynamicSharedMemorySize,
                             SMEM_TOTAL);
        attr_set = true;
    }
    dim3 grid(Ndim / TN, Mdim / TM);             // 16 x 8 = 128 CTAs
    lns_hmma_gemm<<<grid, 128, SMEM_TOTAL>>>(bias, out);
}